// round 1
// baseline (speedup 1.0000x reference)
#include <cuda_runtime.h>
#include <mma.h>
#include <cstdint>

using namespace nvcuda;

#define Bn  4
#define Ln  1024
#define Dn  768
#define Hn  6
#define DHn 128
#define BHn (Bn*Hn)
#define EPSf 1e-5f

#define OFF_CO 0
#define OFF_W  (BHn*Ln*Ln)          /* 25165824 */
#define OFF_V  (OFF_W + Bn*Ln)      /* 25169920 */

// ---------------- scratch (static device allocations; allocation-free at runtime) ----------------
__device__ float  g_S[(size_t)BHn*Ln*Ln];   // ~100 MB fp32 raw scores
__device__ float  g_q2[BHn*Ln];
__device__ float  g_k2[BHn*Ln];
__device__ double g_sum1[Hn];
__device__ double g_sumsq1[Hn];
__device__ float  g_scale1[Hn];
__device__ float  g_shift1[Hn];
__device__ float  g_w[BHn*Ln];              // column sums (B,H,L)
__device__ float  g_scale2[Hn];
__device__ float  g_shift2[Hn];
__device__ float  g_p[Bn*Ln];
__device__ unsigned char g_valid[Bn*Ln];

// ---------------- zero accumulators (graph replays must be idempotent) ----------------
__global__ void zero_kernel() {
    int idx = blockIdx.x*blockDim.x + threadIdx.x;
    if (idx < BHn*Ln) g_w[idx] = 0.f;
    if (idx < Hn) { g_sum1[idx] = 0.0; g_sumsq1[idx] = 0.0; }
}

// ---------------- mask: derive valid[] from bx_packed with dtype sniff ----------------
// bx_packed (B,L), True = padded. Valid pattern is prefix-true per batch, so:
//  - stored as float32: some word equals 0x3f800000 (if any padding); int-nonzero read works too.
//  - stored as uint8  : some 32-bit word > 1 (if any padding) -> byte mode.
//  - stored as int32  : all words in {0,1} -> int mode.
// All-zero (no padding anywhere) is identical under every interpretation.
__global__ void mask_kernel(const unsigned int* w) {
    __shared__ int s_float, s_byte;
    if (threadIdx.x == 0) { s_float = 0; s_byte = 0; }
    __syncthreads();
    for (int i = threadIdx.x; i < (Bn*Ln)/4; i += blockDim.x) {
        unsigned v = w[i];
        if (v == 0x3f800000u) atomicOr(&s_float, 1);
        else if (v > 1u)      atomicOr(&s_byte, 1);
    }
    __syncthreads();
    int byte_mode = (!s_float) && s_byte;
    const unsigned char* bytes = (const unsigned char*)w;
    for (int i = threadIdx.x; i < Bn*Ln; i += blockDim.x) {
        bool padded = byte_mode ? (bytes[i] != 0) : (w[i] != 0u);
        g_valid[i] = padded ? 0 : 1;
    }
}

// ---------------- Vh output: transpose copy (B,L,H,DH) -> (B,H,L,DH) ----------------
__global__ void vout_kernel(const float* __restrict__ V, float* __restrict__ out) {
    int idx = blockIdx.x*blockDim.x + threadIdx.x;          // float4 index
    if (idx >= BHn*Ln*DHn/4) return;
    int d4 = idx & 31;
    int l  = (idx >> 5) & (Ln-1);
    int h  = (idx >> 15) % Hn;
    int b  = idx / (32*Ln*Hn);
    float4 v = *(const float4*)(V + ((size_t)(b*Ln + l))*Dn + h*DHn + d4*4);
    ((float4*)(out + OFF_V))[idx] = v;
}

// ---------------- squared norms per head-row ----------------
__global__ void sq_kernel(const float* __restrict__ Q, const float* __restrict__ K) {
    int warp = (blockIdx.x*blockDim.x + threadIdx.x) >> 5;
    int lane = threadIdx.x & 31;
    if (warp >= 2*BHn*Ln) return;
    int t  = warp / (BHn*Ln);
    int rr = warp % (BHn*Ln);
    int bh = rr / Ln, i = rr % Ln;
    int b = bh / Hn, h = bh % Hn;
    const float* src = (t ? K : Q) + ((size_t)(b*Ln + i))*Dn + h*DHn;
    float4 x = ((const float4*)src)[lane];
    float s = x.x*x.x + x.y*x.y + x.z*x.z + x.w*x.w;
    #pragma unroll
    for (int o = 16; o; o >>= 1) s += __shfl_xor_sync(0xffffffffu, s, o);
    if (lane == 0) (t ? g_k2 : g_q2)[rr] = s;
}

// ---------------- GEMM: S = 2*Q.K^T - q2 - k2, + per-head sum/sumsq (tf32 wmma) ----------------
#define GLD 132   // smem leading dim (128 + 4 pad)
__global__ void __launch_bounds__(256) gemm_kernel(const float* __restrict__ Q,
                                                   const float* __restrict__ K) {
    extern __shared__ float sm[];
    float* Qs = sm;                  // 128 x GLD
    float* Ks = sm + 128*GLD;
    float* Cs = sm + 2*128*GLD;
    int bh = blockIdx.z; int b = bh / Hn, h = bh % Hn;
    int bi0 = blockIdx.y*128, bj0 = blockIdx.x*128;
    const float* Qb = Q + (size_t)b*Ln*Dn + h*DHn;
    const float* Kb = K + (size_t)b*Ln*Dn + h*DHn;

    for (int t = threadIdx.x; t < 128*32; t += 256) {
        int r = t >> 5, c = t & 31;
        float4 q = *(const float4*)(Qb + (size_t)(bi0 + r)*Dn + c*4);
        float4 k = *(const float4*)(Kb + (size_t)(bj0 + r)*Dn + c*4);
        Qs[r*GLD + c*4 + 0] = wmma::__float_to_tf32(q.x);
        Qs[r*GLD + c*4 + 1] = wmma::__float_to_tf32(q.y);
        Qs[r*GLD + c*4 + 2] = wmma::__float_to_tf32(q.z);
        Qs[r*GLD + c*4 + 3] = wmma::__float_to_tf32(q.w);
        Ks[r*GLD + c*4 + 0] = wmma::__float_to_tf32(k.x);
        Ks[r*GLD + c*4 + 1] = wmma::__float_to_tf32(k.y);
        Ks[r*GLD + c*4 + 2] = wmma::__float_to_tf32(k.z);
        Ks[r*GLD + c*4 + 3] = wmma::__float_to_tf32(k.w);
    }
    __syncthreads();

    int warp = threadIdx.x >> 5;
    int wr = warp & 3;      // 4 warps down M (32 rows each)
    int wc = warp >> 2;     // 2 warps across N (64 cols each)

    wmma::fragment<wmma::accumulator, 16,16,8, float> acc[2][4];
    #pragma unroll
    for (int m = 0; m < 2; m++)
        #pragma unroll
        for (int n = 0; n < 4; n++) wmma::fill_fragment(acc[m][n], 0.f);

    #pragma unroll
    for (int k = 0; k < 128; k += 8) {
        wmma::fragment<wmma::matrix_a, 16,16,8, wmma::precision::tf32, wmma::row_major> af[2];
        wmma::fragment<wmma::matrix_b, 16,16,8, wmma::precision::tf32, wmma::col_major> bf[4];
        #pragma unroll
        for (int m = 0; m < 2; m++)
            wmma::load_matrix_sync(af[m], Qs + (wr*32 + m*16)*GLD + k, GLD);
        #pragma unroll
        for (int n = 0; n < 4; n++)
            wmma::load_matrix_sync(bf[n], Ks + (wc*64 + n*16)*GLD + k, GLD);
        #pragma unroll
        for (int m = 0; m < 2; m++)
            #pragma unroll
            for (int n = 0; n < 4; n++)
                wmma::mma_sync(acc[m][n], af[m], bf[n], acc[m][n]);
    }
    __syncthreads();   // Qs/Ks no longer needed before Cs writes? Cs is separate; sync for frag stores ordering
    #pragma unroll
    for (int m = 0; m < 2; m++)
        #pragma unroll
        for (int n = 0; n < 4; n++)
            wmma::store_matrix_sync(Cs + (wr*32 + m*16)*GLD + wc*64 + n*16, acc[m][n], GLD,
                                    wmma::mem_row_major);
    __syncthreads();

    const float* q2r = g_q2 + bh*Ln + bi0;
    const float* k2r = g_k2 + bh*Ln + bj0;
    float* Sout = g_S + ((size_t)bh*Ln + bi0)*Ln + bj0;
    float lsum = 0.f, lsq = 0.f;
    for (int t = threadIdx.x; t < 128*128; t += 256) {
        int i = t >> 7, j = t & 127;
        float s = 2.f*Cs[i*GLD + j] - q2r[i] - k2r[j];
        Sout[(size_t)i*Ln + j] = s;
        lsum += s; lsq += s*s;
    }
    // block reduce (double)
    double ds = (double)lsum, dq = (double)lsq;
    #pragma unroll
    for (int o = 16; o; o >>= 1) {
        ds += __shfl_xor_sync(0xffffffffu, ds, o);
        dq += __shfl_xor_sync(0xffffffffu, dq, o);
    }
    __shared__ double rs[8], rq[8];
    int lane = threadIdx.x & 31;
    if (lane == 0) { rs[warp] = ds; rq[warp] = dq; }
    __syncthreads();
    if (warp == 0) {
        ds = (lane < 8) ? rs[lane] : 0.0;
        dq = (lane < 8) ? rq[lane] : 0.0;
        #pragma unroll
        for (int o = 4; o; o >>= 1) {
            ds += __shfl_xor_sync(0xffffffffu, ds, o);
            dq += __shfl_xor_sync(0xffffffffu, dq, o);
        }
        if (lane == 0) { atomicAdd(&g_sum1[h], ds); atomicAdd(&g_sumsq1[h], dq); }
    }
}

// ---------------- BN1 stats finalize ----------------
__global__ void stats1_kernel(const float* __restrict__ g1, const float* __restrict__ b1) {
    int h = threadIdx.x;
    if (h < Hn) {
        double n = (double)Bn*Ln*Ln;
        double m = g_sum1[h]/n;
        double var = g_sumsq1[h]/n - m*m;
        float rstd = (float)rsqrt(var + (double)EPSf);
        g_scale1[h] = g1[h]*rstd;
        g_shift1[h] = b1[h] - (float)m*rstd*g1[h];
    }
}

// ---------------- normalize + mask(0) + softmax + column sums ----------------
__global__ void __launch_bounds__(512) softmax_kernel(float* __restrict__ co) {
    __shared__ float colsum[Ln];
    __shared__ unsigned char sval[Ln];
    int bh = blockIdx.x >> 6;       // 64 row-blocks per (b,h)
    int rb = blockIdx.x & 63;
    int b = bh / Hn, h = bh % Hn;
    int tid = threadIdx.x, warp = tid >> 5, lane = tid & 31;
    for (int j = tid; j < Ln; j += 512) { colsum[j] = 0.f; sval[j] = g_valid[b*Ln + j]; }
    __syncthreads();

    int i = rb*16 + warp;
    bool rowvalid = sval[i] != 0;
    float scale = g_scale1[h], shift = g_shift1[h];
    const float4* Sr = (const float4*)(g_S + ((size_t)bh*Ln + i)*Ln);

    float v[32];
    float mx = -1e30f;
    #pragma unroll
    for (int c = 0; c < 8; c++) {
        float4 x = Sr[c*32 + lane];
        int j0 = c*128 + lane*4;
        float a0 = (rowvalid && sval[j0+0]) ? x.x*scale + shift : 0.f;
        float a1 = (rowvalid && sval[j0+1]) ? x.y*scale + shift : 0.f;
        float a2 = (rowvalid && sval[j0+2]) ? x.z*scale + shift : 0.f;
        float a3 = (rowvalid && sval[j0+3]) ? x.w*scale + shift : 0.f;
        v[c*4+0]=a0; v[c*4+1]=a1; v[c*4+2]=a2; v[c*4+3]=a3;
        mx = fmaxf(mx, fmaxf(fmaxf(a0,a1), fmaxf(a2,a3)));
    }
    #pragma unroll
    for (int o = 16; o; o >>= 1) mx = fmaxf(mx, __shfl_xor_sync(0xffffffffu, mx, o));
    float sum = 0.f;
    #pragma unroll
    for (int t = 0; t < 32; t++) { float e = __expf(v[t] - mx); v[t] = e; sum += e; }
    #pragma unroll
    for (int o = 16; o; o >>= 1) sum += __shfl_xor_sync(0xffffffffu, sum, o);
    float inv = 1.0f / sum;

    float4* Cr = (float4*)(co + ((size_t)bh*Ln + i)*Ln);
    #pragma unroll
    for (int c = 0; c < 8; c++) {
        int j0 = c*128 + lane*4;
        float4 o4;
        o4.x = v[c*4+0]*inv; o4.y = v[c*4+1]*inv; o4.z = v[c*4+2]*inv; o4.w = v[c*4+3]*inv;
        Cr[c*32 + lane] = o4;
        atomicAdd(&colsum[j0+0], o4.x);
        atomicAdd(&colsum[j0+1], o4.y);
        atomicAdd(&colsum[j0+2], o4.z);
        atomicAdd(&colsum[j0+3], o4.w);
    }
    __syncthreads();
    for (int j = tid; j < Ln; j += 512) atomicAdd(&g_w[bh*Ln + j], colsum[j]);
}

// ---------------- BN2 stats (per head over B*L) ----------------
__global__ void stats2_kernel(const float* __restrict__ g2, const float* __restrict__ b2) {
    int h = blockIdx.x;
    int tid = threadIdx.x;
    float ls = 0.f, lq = 0.f;
    for (int b = 0; b < Bn; b++) {
        const float* wp = g_w + (b*Hn + h)*Ln;
        for (int j = tid; j < Ln; j += 256) { float x = wp[j]; ls += x; lq += x*x; }
    }
    double ds = (double)ls, dq = (double)lq;
    #pragma unroll
    for (int o = 16; o; o >>= 1) {
        ds += __shfl_xor_sync(0xffffffffu, ds, o);
        dq += __shfl_xor_sync(0xffffffffu, dq, o);
    }
    __shared__ double rs[8], rq[8];
    int warp = tid >> 5, lane = tid & 31;
    if (lane == 0) { rs[warp] = ds; rq[warp] = dq; }
    __syncthreads();
    if (tid == 0) {
        double S = 0.0, Q2 = 0.0;
        for (int wgi = 0; wgi < 8; wgi++) { S += rs[wgi]; Q2 += rq[wgi]; }
        double n = (double)Bn*Ln;
        double m = S/n;
        double var = Q2/n - m*m;
        float rstd = (float)rsqrt(var + (double)EPSf);
        g_scale2[h] = g2[h]*rstd;
        g_shift2[h] = b2[h] - (float)m*rstd*g2[h];
    }
}

// ---------------- posterior gate: Linear(H,2) + 2-class softmax -> p0 ----------------
__global__ void gate_kernel(const float* __restrict__ Wp, const float* __restrict__ bp) {
    int idx = blockIdx.x*blockDim.x + threadIdx.x;
    if (idx >= Bn*Ln) return;
    int b = idx >> 10, l = idx & (Ln-1);
    float z0 = bp[0], z1 = bp[1];
    #pragma unroll
    for (int h = 0; h < Hn; h++) {
        float wn = g_w[(b*Hn + h)*Ln + l]*g_scale2[h] + g_shift2[h];
        z0 += Wp[h]      * wn;
        z1 += Wp[Hn + h] * wn;
    }
    float d = z1 - z0;
    g_p[idx] = 1.f/(1.f + __expf(d));
}

// ---------------- final masked softmax over L per batch ----------------
__global__ void final_kernel(float* __restrict__ out) {
    int b = blockIdx.x, l = threadIdx.x;
    __shared__ float redm[32], redsum[32], bc[2];
    const float NEG_INF = __int_as_float(0xff800000);
    float x = g_valid[b*Ln + l] ? g_p[b*Ln + l] : NEG_INF;
    int warp = l >> 5, lane = l & 31;
    float m = x;
    #pragma unroll
    for (int o = 16; o; o >>= 1) m = fmaxf(m, __shfl_xor_sync(0xffffffffu, m, o));
    if (lane == 0) redm[warp] = m;
    __syncthreads();
    if (warp == 0) {
        m = redm[lane];
        #pragma unroll
        for (int o = 16; o; o >>= 1) m = fmaxf(m, __shfl_xor_sync(0xffffffffu, m, o));
        if (lane == 0) bc[0] = m;
    }
    __syncthreads();
    m = bc[0];
    float e = __expf(x - m);     // exp(-inf)=0 for padded
    float s = e;
    #pragma unroll
    for (int o = 16; o; o >>= 1) s += __shfl_xor_sync(0xffffffffu, s, o);
    if (lane == 0) redsum[warp] = s;
    __syncthreads();
    if (warp == 0) {
        s = redsum[lane];
        #pragma unroll
        for (int o = 16; o; o >>= 1) s += __shfl_xor_sync(0xffffffffu, s, o);
        if (lane == 0) bc[1] = s;
    }
    __syncthreads();
    out[OFF_W + b*Ln + l] = e / bc[1];
}

// ---------------- launch ----------------
extern "C" void kernel_launch(void* const* d_in, const int* in_sizes, int n_in,
                              void* d_out, int out_size) {
    const float* Q  = (const float*)d_in[0];
    const float* K  = (const float*)d_in[1];
    const float* V  = (const float*)d_in[2];
    const unsigned int* bx = (const unsigned int*)d_in[4];   // bx_packed (dtype sniffed)
    const float* g1 = (const float*)d_in[5];
    const float* b1 = (const float*)d_in[6];
    const float* g2 = (const float*)d_in[7];
    const float* b2 = (const float*)d_in[8];
    const float* Wp = (const float*)d_in[9];
    const float* bp = (const float*)d_in[10];
    float* out = (float*)d_out;

    cudaFuncSetAttribute(gemm_kernel, cudaFuncAttributeMaxDynamicSharedMemorySize, 3*128*GLD*4);

    zero_kernel<<<(BHn*Ln + 255)/256, 256>>>();
    mask_kernel<<<1, 256>>>(bx);
    vout_kernel<<<(BHn*Ln*DHn/4 + 255)/256, 256>>>(V, out);
    sq_kernel<<<(2*BHn*Ln*32 + 255)/256, 256>>>(Q, K);
    dim3 gg(Ln/128, Ln/128, BHn);
    gemm_kernel<<<gg, 256, 3*128*GLD*4>>>(Q, K);
    stats1_kernel<<<1, 32>>>(g1, b1);
    softmax_kernel<<<BHn*(Ln/16), 512>>>(out);
    stats2_kernel<<<Hn, 256>>>(g2, b2);
    gate_kernel<<<(Bn*Ln + 255)/256, 256>>>(Wp, bp);
    final_kernel<<<Bn, Ln>>>(out);
}